// round 17
// baseline (speedup 1.0000x reference)
#include <cuda_runtime.h>
#include <cstdint>

#define HW 50176            // 224*224
#define S_BANDS 371
#define LUT_N 512

// 2*pi*H*C*1e9 * STRESS_MAGNITUDE
#define PHASE_SCALE 15833.626974092555f

#define MM_BLOCKS 49                     // 49*256 threads, 1 float4 each = 12544
#define ENT_PER_BLK 8                    // LUT entries per block (1 warp/entry)
#define BANDS_PER_SEG 12                 // 32 lanes * 12 = 384 >= 371
#define LUT_BLOCKS (LUT_N / ENT_PER_BLK)         // 64
#define K12_BLOCKS (MM_BLOCKS + LUT_BLOCKS)      // 113 blocks, one wave

// Per-block / per-entry partial results — plain stores, fully overwritten
// every replay. NO atomics, NO reset logic anywhere.
static __device__ float  g_pmin[MM_BLOCKS];     // block minima
static __device__ float  g_pmax[MM_BLOCKS];     // block maxima
static __device__ float  g_pemax[LUT_N];        // per-ENTRY max of F (512)
static __device__ float4 g_lut[LUT_N];          // {F0, F1, F2, pad}

// ---------------------------------------------------------------------------
// K12: fused min/max + LUT build on disjoint block ranges. 113 blocks -> one
// wave. Implicit PSS trigger at block completion releases the pixel kernel.
//   blocks [0,49):   block min/max of stressmap -> g_pmin/g_pmax (plain STG)
//   blocks [49,113): LUT, one WARP per entry: each lane loads its 12 bands
//                    straight from gmem (no smem, no block barrier), 12-band
//                    MUFU chain, 5-step shfl fold, lane0 stores entry + max.
// ---------------------------------------------------------------------------
__global__ void __launch_bounds__(256) k12_kernel(const float* __restrict__ sm,
                                                  const float* __restrict__ ss) {
    const int tid  = threadIdx.x;
    const int lane = tid & 31;
    const int wrp  = tid >> 5;

    if (blockIdx.x < MM_BLOCKS) {
        __shared__ float s_mn[8], s_mx[8];
        const int i = blockIdx.x * 256 + tid;          // 0 .. 12543
        float4 v = ((const float4*)sm)[i];
        float mn = fminf(fminf(v.x, v.y), fminf(v.z, v.w));
        float mx = fmaxf(fmaxf(v.x, v.y), fmaxf(v.z, v.w));
        #pragma unroll
        for (int o = 16; o; o >>= 1) {
            mn = fminf(mn, __shfl_xor_sync(0xFFFFFFFFu, mn, o));
            mx = fmaxf(mx, __shfl_xor_sync(0xFFFFFFFFu, mx, o));
        }
        if (lane == 0) { s_mn[wrp] = mn; s_mx[wrp] = mx; }
        __syncthreads();
        if (tid == 0) {
            float bmn = s_mn[0], bmx = s_mx[0];
            #pragma unroll
            for (int w = 1; w < 8; w++) {
                bmn = fminf(bmn, s_mn[w]);
                bmx = fmaxf(bmx, s_mx[w]);
            }
            g_pmin[blockIdx.x] = bmn;                  // plain stores
            g_pmax[blockIdx.x] = bmx;
        }
    } else {
        // one warp per LUT entry — fully independent, no smem, no barriers
        const int i = (blockIdx.x - MM_BLOCKS) * ENT_PER_BLK + wrp;   // LUT idx
        const float t = (float)i * (PHASE_SCALE / (float)(LUT_N - 1));

        const int s0 = lane * BANDS_PER_SEG;
        int sN = S_BANDS - s0;                          // bands for this lane
        if (sN < 0) sN = 0;
        if (sN > BANDS_PER_SEG) sN = BANDS_PER_SEG;

        // partial of sum_s w_sc*(1 - cos(t/lam_s)), bands loaded directly
        float a0 = 0.f, a1 = 0.f, a2 = 0.f;
        const float* w = ss + 3 * s0;
        #pragma unroll 4
        for (int j = 0; j < sN; j++) {
            const float lam = 390.0f + (float)(s0 + j);
            const float c = 1.0f - __cosf(t / lam);
            a0 = fmaf(w[3 * j + 0], c, a0);
            a1 = fmaf(w[3 * j + 1], c, a1);
            a2 = fmaf(w[3 * j + 2], c, a2);
        }
        #pragma unroll
        for (int o = 16; o; o >>= 1) {
            a0 += __shfl_xor_sync(0xFFFFFFFFu, a0, o);
            a1 += __shfl_xor_sync(0xFFFFFFFFu, a1, o);
            a2 += __shfl_xor_sync(0xFFFFFFFFu, a2, o);
        }
        if (lane == 0) {
            const float F0 = 0.5f * a0, F1 = 0.5f * a1, F2 = 0.5f * a2;
            g_lut[i]   = make_float4(F0, F1, F2, 0.f);
            g_pemax[i] = fmaxf(F0, fmaxf(F1, F2));     // per-entry max
        }
    }
}

// ---------------------------------------------------------------------------
// K3: per-pixel lerp + normalize + store, x2 (float2), PDL-launched.
// Input load issued BEFORE cudaGridDependencySynchronize(). After the sync,
// warps 0..2 reduce the partials (min / max / 512 entry-maxima) in parallel;
// one smem barrier broadcasts the 3 scalars. No tail work at all.
// ---------------------------------------------------------------------------
__global__ void __launch_bounds__(256) pixel_kernel(const float* __restrict__ sm,
                                                    float* __restrict__ out) {
    __shared__ float s_red[3];     // {min, max, lutmax}
    const int tid  = threadIdx.x;
    const int lane = tid & 31;
    const int wrp  = tid >> 5;
    const int p2   = blockIdx.x * 256 + tid;         // 0 .. 25087

    const float2 x = ((const float2*)sm)[p2];        // independent of K12

    cudaGridDependencySynchronize();                 // K12's writes now visible

    if (wrp == 0) {                                  // reduce 49 block minima
        float v = (lane < MM_BLOCKS) ? g_pmin[lane] : 3.4e38f;
        if (lane + 32 < MM_BLOCKS) v = fminf(v, g_pmin[lane + 32]);
        #pragma unroll
        for (int o = 16; o; o >>= 1) v = fminf(v, __shfl_xor_sync(0xFFFFFFFFu, v, o));
        if (lane == 0) s_red[0] = v;
    } else if (wrp == 1) {                           // reduce 49 block maxima
        float v = (lane < MM_BLOCKS) ? g_pmax[lane] : 0.f;
        if (lane + 32 < MM_BLOCKS) v = fmaxf(v, g_pmax[lane + 32]);
        #pragma unroll
        for (int o = 16; o; o >>= 1) v = fmaxf(v, __shfl_xor_sync(0xFFFFFFFFu, v, o));
        if (lane == 0) s_red[1] = v;
    } else if (wrp == 2) {                           // reduce 512 entry maxima
        const float4* pe4 = (const float4*)g_pemax;  // 128 float4s
        float v = 0.f;
        #pragma unroll
        for (int j = 0; j < 4; j++) {                // 4 independent LDG.128
            float4 f = pe4[j * 32 + lane];
            v = fmaxf(v, fmaxf(fmaxf(f.x, f.y), fmaxf(f.z, f.w)));
        }
        #pragma unroll
        for (int o = 16; o; o >>= 1) v = fmaxf(v, __shfl_xor_sync(0xFFFFFFFFu, v, o));
        if (lane == 0) s_red[2] = v;
    }
    __syncthreads();

    const float mn     = s_red[0];
    const float invrng = (float)(LUT_N - 1) / (s_red[1] - mn);
    const float inv    = 1.0f / s_red[2];

    float r0[2], r1[2], r2[2];
    const float xs[2] = {x.x, x.y};
    #pragma unroll
    for (int k = 0; k < 2; k++) {
        float u = (xs[k] - mn) * invrng;             // 0 .. LUT_N-1
        int   i = (int)u;
        i = (i < 0) ? 0 : ((i > LUT_N - 2) ? LUT_N - 2 : i);
        float fr = u - (float)i;
        float4 a = g_lut[i];
        float4 b = g_lut[i + 1];
        r0[k] = fmaf(fr, b.x - a.x, a.x) * inv;
        r1[k] = fmaf(fr, b.y - a.y, a.y) * inv;
        r2[k] = fmaf(fr, b.z - a.z, a.z) * inv;
    }

    float2* o2 = (float2*)out;
    o2[p2]          = make_float2(r0[0], r0[1]);
    o2[HW / 2 + p2] = make_float2(r1[0], r1[1]);
    o2[HW + p2]     = make_float2(r2[0], r2[1]);
    // no tail: nothing to reset, kernel ends at the last store.
}

extern "C" void kernel_launch(void* const* d_in, const int* in_sizes, int n_in,
                              void* d_out, int out_size) {
    const float* sm = (const float*)d_in[0];
    const float* ss = (const float*)d_in[1];
    if (in_sizes[0] != HW) {   // defensive: identify by element count
        sm = (const float*)d_in[1];
        ss = (const float*)d_in[0];
    }
    float* out = (float*)d_out;

    k12_kernel<<<K12_BLOCKS, 256>>>(sm, ss);         // 113 blocks, one wave

    // PDL: pixel kernel launches early (implicit trigger at K12 block
    // completion); orders itself via griddepsync.
    cudaLaunchConfig_t cfg = {};
    cfg.gridDim  = dim3(HW / 2 / 256);               // 98 blocks
    cfg.blockDim = dim3(256);
    cudaLaunchAttribute attr[1];
    attr[0].id = cudaLaunchAttributeProgrammaticStreamSerialization;
    attr[0].val.programmaticStreamSerializationAllowed = 1;
    cfg.attrs = attr;
    cfg.numAttrs = 1;
    cudaLaunchKernelEx(&cfg, pixel_kernel, sm, out);
}